// round 12
// baseline (speedup 1.0000x reference)
#include <cuda_runtime.h>

#define BATCH   262144
#define T_STEPS 20
#define THRESHF 1.0f

using u32 = unsigned int;
using u64 = unsigned long long;

__device__ __forceinline__ u64 pack2(float lo, float hi) {
    u64 r; asm("mov.b64 %0, {%1, %2};" : "=l"(r) : "f"(lo), "f"(hi)); return r;
}
__device__ __forceinline__ void unpack2(u64 v, float &lo, float &hi) {
    asm("mov.b64 {%0, %1}, %2;" : "=f"(lo), "=f"(hi) : "l"(v));
}
__device__ __forceinline__ u64 packi(u32 lo, u32 hi) {
    u64 r; asm("mov.b64 %0, {%1, %2};" : "=l"(r) : "r"(lo), "r"(hi)); return r;
}
__device__ __forceinline__ void unpacki(u64 v, u32 &lo, u32 &hi) {
    asm("mov.b64 {%0, %1}, %2;" : "=r"(lo), "=r"(hi) : "l"(v));
}
// Packed dual fp32 FMA / ADD (fma pipe, 2 lanes per instruction)
__device__ __forceinline__ u64 ffma2(u64 a, u64 b, u64 c) {
    u64 d; asm("fma.rn.f32x2 %0, %1, %2, %3;" : "=l"(d) : "l"(a), "l"(b), "l"(c)); return d;
}
__device__ __forceinline__ u64 add2(u64 a, u64 b) {
    u64 d; asm("add.rn.f32x2 %0, %1, %2;" : "=l"(d) : "l"(a), "l"(b)); return d;
}
// Predicated packed adds: one setp shared across 4/2/1 adds.
// Exact: acc+w == fma(1,w,acc); skipped == fma(0,w,acc).
__device__ __forceinline__ void padd4(u64 &a0, u64 &a1, u64 &a2, u64 &a3, u32 cond,
                                      u64 w0, u64 w1, u64 w2, u64 w3) {
    asm("{ .reg .pred p;\n\t"
        "setp.ne.u32 p, %8, 0;\n\t"
        "@p add.rn.f32x2 %0, %0, %4;\n\t"
        "@p add.rn.f32x2 %1, %1, %5;\n\t"
        "@p add.rn.f32x2 %2, %2, %6;\n\t"
        "@p add.rn.f32x2 %3, %3, %7; }"
        : "+l"(a0), "+l"(a1), "+l"(a2), "+l"(a3)
        : "l"(w0), "l"(w1), "l"(w2), "l"(w3), "r"(cond));
}
__device__ __forceinline__ void padd2(u64 &a0, u64 &a1, u32 cond, u64 w0, u64 w1) {
    asm("{ .reg .pred p;\n\t"
        "setp.ne.u32 p, %4, 0;\n\t"
        "@p add.rn.f32x2 %0, %0, %2;\n\t"
        "@p add.rn.f32x2 %1, %1, %3; }"
        : "+l"(a0), "+l"(a1) : "l"(w0), "l"(w1), "r"(cond));
}
__device__ __forceinline__ void padd1(u64 &a0, u32 cond, u64 w0) {
    asm("{ .reg .pred p;\n\t"
        "setp.ne.u32 p, %2, 0;\n\t"
        "@p add.rn.f32x2 %0, %0, %1; }"
        : "+l"(a0) : "l"(w0), "r"(cond));
}

#define BETA2 0x3F6666663F666666ull   // (0.9f, 0.9f)

// ---- static smem weights, quarter-contiguous (warp-uniform addressing) ----
__shared__ u64 sW1[4 * 10 * 8];  // 10 -> 64, P4=8
__shared__ u64 sW2[4 * 64 * 4];  // 64 -> 32, P4=4
__shared__ u64 sW3[4 * 32 * 4];  // 32 -> 32, P4=4
__shared__ u64 sW4[4 * 32 * 2];  // 32 -> 16, P4=2
__shared__ u64 sW5[4 * 16 * 1];  // 16 -> 6 (padded to 8), P4=1
// spike-mask exchange: [region][wq][lane][el0,el1] (u32 units; u64 accesses)
__shared__ u32 spk[4 * 4 * 32 * 2];

__device__ __forceinline__ void stage(u64* dst, const float* __restrict__ W,
                                      int NIN, int NOUT, int P4, int tid) {
    int total = 4 * NIN * P4;
    for (int idx = tid; idx < total; idx += 128) {
        int q = idx / (NIN * P4);
        int r = idx % (NIN * P4);
        int i = r / P4, p = r % P4;
        int j0 = q * (2 * P4) + 2 * p;
        float a = (j0     < NOUT) ? W[j0 * NIN + i]       : 0.0f;
        float b = (j0 + 1 < NOUT) ? W[(j0 + 1) * NIN + i] : 0.0f;
        dst[idx] = pack2(a, b);
    }
}

// Packed LIF: reset from OLD m (subtract), update, return 2-bit spike mask.
// a + (-1.0f) == a - 1.0f exactly; a + 0.0f differs from a - 0.0f only in zero
// sign, which can never flip a (> 1.0) compare -> outputs bit-identical.
__device__ __forceinline__ u32 lif_pk(u64 acc, u64 &m) {
    float mlo, mhi; unpack2(m, mlo, mhi);
    float nr0 = mlo > THRESHF ? -1.0f : 0.0f;
    float nr1 = mhi > THRESHF ? -1.0f : 0.0f;
    m = ffma2(BETA2, m, add2(acc, pack2(nr0, nr1)));
    float o0, o1; unpack2(m, o0, o1);
    u32 k = 0;
    if (o0 > THRESHF) k |= 1u;
    if (o1 > THRESHF) k |= 2u;
    return k;
}

__global__ __launch_bounds__(128, 3) void lif_kernel(
    const float* __restrict__ x,
    const float* __restrict__ W1, const float* __restrict__ W2,
    const float* __restrict__ W3, const float* __restrict__ W4,
    const float* __restrict__ W5, float* __restrict__ out)
{
    const int tid = threadIdx.x;
    stage(sW1, W1, 10, 64, 8, tid);
    stage(sW2, W2, 64, 32, 4, tid);
    stage(sW3, W3, 32, 32, 4, tid);
    stage(sW4, W4, 32, 16, 2, tid);
    stage(sW5, W5, 16,  6, 1, tid);
    __syncthreads();

    const int wq   = tid >> 5;      // warp = quarter of every layer's outputs
    const int lane = tid & 31;
    const size_t eglob = (size_t)blockIdx.x * 64 + lane * 2;  // elements 2*lane, 2*lane+1

    const u64* w1 = sW1 + wq * (10 * 8);
    const u64* w2 = sW2 + wq * (64 * 4);
    const u64* w3 = sW3 + wq * (32 * 4);
    const u64* w4 = sW4 + wq * (32 * 2);
    const u64* w5 = sW5 + wq * 16;
    u32* sp1 = spk;           // each region: [4 wq][32 lane][2 el]
    u32* sp2 = spk + 256;
    u32* sp3 = spk + 512;
    u32* sp4 = spk + 768;
    const int myoff = wq * 64 + lane * 2;   // producer u32 offset (u64-aligned)

    // membrane state as packed pairs: quarter of every layer, E=2 elements
    u64 m1[2][8], m2[2][4], m3[2][4], m4[2][2], m5[2][1];
#pragma unroll
    for (int el = 0; el < 2; ++el) {
#pragma unroll
        for (int k = 0; k < 8; ++k) m1[el][k] = 0ull;
#pragma unroll
        for (int k = 0; k < 4; ++k) { m2[el][k] = 0ull; m3[el][k] = 0ull; }
#pragma unroll
        for (int k = 0; k < 2; ++k)  m4[el][k] = 0ull;
        m5[el][0] = 0ull;
    }

#pragma unroll 1
    for (int t = 0; t < T_STEPS; ++t) {
        // ================= Layer 1: 10 -> 64 (8 pairs per warp) =================
        u32 m16[2];
#pragma unroll
        for (int el = 0; el < 2; ++el) {
            const float2* xp = (const float2*)(x + ((size_t)t * BATCH + eglob + el) * 10);
            float2 xv[5];
#pragma unroll
            for (int i = 0; i < 5; ++i) xv[i] = xp[i];

            u64 acc[8];
#pragma unroll
            for (int p = 0; p < 8; ++p) acc[p] = 0ull;
#pragma unroll
            for (int i = 0; i < 10; ++i) {
                const ulonglong2* wp = (const ulonglong2*)(w1 + i * 8);
                ulonglong2 wa = wp[0], wb = wp[1], wc = wp[2], wd = wp[3];
                float xf = (i & 1) ? xv[i >> 1].y : xv[i >> 1].x;
                u64 xd = pack2(xf, xf);
                acc[0] = ffma2(xd, wa.x, acc[0]);
                acc[1] = ffma2(xd, wa.y, acc[1]);
                acc[2] = ffma2(xd, wb.x, acc[2]);
                acc[3] = ffma2(xd, wb.y, acc[3]);
                acc[4] = ffma2(xd, wc.x, acc[4]);
                acc[5] = ffma2(xd, wc.y, acc[5]);
                acc[6] = ffma2(xd, wd.x, acc[6]);
                acc[7] = ffma2(xd, wd.y, acc[7]);
            }
            u32 mk = 0;
#pragma unroll
            for (int p = 0; p < 8; ++p)
                mk |= lif_pk(acc[p], m1[el][p]) << (2 * p);
            m16[el] = mk;
        }
        {   // store both elements' pre-shifted words as one STS.64
            u32 s0 = (wq & 1) ? (m16[0] << 16) : m16[0];
            u32 s1 = (wq & 1) ? (m16[1] << 16) : m16[1];
            *(u64*)(sp1 + myoff) = packi(s0, s1);
        }
        __syncthreads();
        u32 lo[2], hi[2];
        {
            u64 v0 = *(const u64*)(sp1 + 0 * 64 + lane * 2);
            u64 v1 = *(const u64*)(sp1 + 1 * 64 + lane * 2);
            u64 v2 = *(const u64*)(sp1 + 2 * 64 + lane * 2);
            u64 v3 = *(const u64*)(sp1 + 3 * 64 + lane * 2);
            u64 vlo = v0 | v1, vhi = v2 | v3;
            unpacki(vlo, lo[0], lo[1]);   // L1 outputs 0..31 per element
            unpacki(vhi, hi[0], hi[1]);   // L1 outputs 32..63 per element
        }

        // ================= Layer 2: 64 -> 32 (4 pairs per warp) =================
        u64 acc2[2][4];
#pragma unroll
        for (int el = 0; el < 2; ++el)
#pragma unroll
            for (int p = 0; p < 4; ++p) acc2[el][p] = 0ull;
#pragma unroll
        for (int i = 0; i < 64; ++i) {
            const ulonglong2* wp = (const ulonglong2*)(w2 + i * 4);
            ulonglong2 wa = wp[0], wb = wp[1];
            u32 bit = 1u << (i & 31);
            u32 c0 = ((i < 32) ? lo[0] : hi[0]) & bit;
            u32 c1 = ((i < 32) ? lo[1] : hi[1]) & bit;
            padd4(acc2[0][0], acc2[0][1], acc2[0][2], acc2[0][3], c0, wa.x, wa.y, wb.x, wb.y);
            padd4(acc2[1][0], acc2[1][1], acc2[1][2], acc2[1][3], c1, wa.x, wa.y, wb.x, wb.y);
        }
        {
            u32 w0 = 0, w1m = 0;
#pragma unroll
            for (int p = 0; p < 4; ++p) {
                w0  |= lif_pk(acc2[0][p], m2[0][p]) << (2 * p);
                w1m |= lif_pk(acc2[1][p], m2[1][p]) << (2 * p);
            }
            *(u64*)(sp2 + myoff) = packi(w0 << (wq * 8), w1m << (wq * 8));
        }
        __syncthreads();
        u32 f2[2];
        {
            u64 v = (*(const u64*)(sp2 + 0 * 64 + lane * 2))
                  | (*(const u64*)(sp2 + 1 * 64 + lane * 2))
                  | (*(const u64*)(sp2 + 2 * 64 + lane * 2))
                  | (*(const u64*)(sp2 + 3 * 64 + lane * 2));
            unpacki(v, f2[0], f2[1]);
        }

        // ================= Layer 3: 32 -> 32 =================
        u64 acc3[2][4];
#pragma unroll
        for (int el = 0; el < 2; ++el)
#pragma unroll
            for (int p = 0; p < 4; ++p) acc3[el][p] = 0ull;
#pragma unroll
        for (int i = 0; i < 32; ++i) {
            const ulonglong2* wp = (const ulonglong2*)(w3 + i * 4);
            ulonglong2 wa = wp[0], wb = wp[1];
            u32 bit = 1u << i;
            padd4(acc3[0][0], acc3[0][1], acc3[0][2], acc3[0][3], f2[0] & bit,
                  wa.x, wa.y, wb.x, wb.y);
            padd4(acc3[1][0], acc3[1][1], acc3[1][2], acc3[1][3], f2[1] & bit,
                  wa.x, wa.y, wb.x, wb.y);
        }
        {
            u32 w0 = 0, w1m = 0;
#pragma unroll
            for (int p = 0; p < 4; ++p) {
                w0  |= lif_pk(acc3[0][p], m3[0][p]) << (2 * p);
                w1m |= lif_pk(acc3[1][p], m3[1][p]) << (2 * p);
            }
            *(u64*)(sp3 + myoff) = packi(w0 << (wq * 8), w1m << (wq * 8));
        }
        __syncthreads();
        u32 f3[2];
        {
            u64 v = (*(const u64*)(sp3 + 0 * 64 + lane * 2))
                  | (*(const u64*)(sp3 + 1 * 64 + lane * 2))
                  | (*(const u64*)(sp3 + 2 * 64 + lane * 2))
                  | (*(const u64*)(sp3 + 3 * 64 + lane * 2));
            unpacki(v, f3[0], f3[1]);
        }

        // ================= Layer 4: 32 -> 16 (2 pairs per warp) =================
        u64 acc4[2][2];
#pragma unroll
        for (int el = 0; el < 2; ++el) { acc4[el][0] = 0ull; acc4[el][1] = 0ull; }
#pragma unroll
        for (int i = 0; i < 32; ++i) {
            const ulonglong2* wp = (const ulonglong2*)(w4 + i * 2);
            ulonglong2 wa = wp[0];
            u32 bit = 1u << i;
            padd2(acc4[0][0], acc4[0][1], f3[0] & bit, wa.x, wa.y);
            padd2(acc4[1][0], acc4[1][1], f3[1] & bit, wa.x, wa.y);
        }
        {
            u32 w0 = lif_pk(acc4[0][0], m4[0][0]) | (lif_pk(acc4[0][1], m4[0][1]) << 2);
            u32 w1m = lif_pk(acc4[1][0], m4[1][0]) | (lif_pk(acc4[1][1], m4[1][1]) << 2);
            *(u64*)(sp4 + myoff) = packi(w0 << (wq * 4), w1m << (wq * 4));
        }
        __syncthreads();
        u32 f4[2];
        {
            u64 v = (*(const u64*)(sp4 + 0 * 64 + lane * 2))
                  | (*(const u64*)(sp4 + 1 * 64 + lane * 2))
                  | (*(const u64*)(sp4 + 2 * 64 + lane * 2))
                  | (*(const u64*)(sp4 + 3 * 64 + lane * 2));
            unpacki(v, f4[0], f4[1]);
        }

        // ================= Layer 5: 16 -> 6 (padded; 1 pair per warp) ============
        u64 acc5[2];
        acc5[0] = 0ull; acc5[1] = 0ull;
#pragma unroll
        for (int i = 0; i < 16; ++i) {
            u64 w = w5[i];
            u32 bit = 1u << i;
            padd1(acc5[0], f4[0] & bit, w);
            padd1(acc5[1], f4[1] & bit, w);
        }
#pragma unroll
        for (int el = 0; el < 2; ++el) {
            float mlo, mhi; unpack2(m5[el][0], mlo, mhi);
            float nr0 = mlo > THRESHF ? -1.0f : 0.0f;
            float nr1 = mhi > THRESHF ? -1.0f : 0.0f;
            m5[el][0] = ffma2(BETA2, m5[el][0], add2(acc5[el], pack2(nr0, nr1)));
            float o0, o1; unpack2(m5[el][0], o0, o1);
            if (wq < 3) {
                float2 o;
                o.x = o0 > THRESHF ? 1.0f : 0.0f;
                o.y = o1 > THRESHF ? 1.0f : 0.0f;
                *(float2*)(out + ((size_t)t * BATCH + eglob + el) * 6 + wq * 2) = o;
            }
        }
    }
}

extern "C" void kernel_launch(void* const* d_in, const int* in_sizes, int n_in,
                              void* d_out, int out_size) {
    const float *x = nullptr, *W1 = nullptr, *W2 = nullptr, *W3 = nullptr,
                *W4 = nullptr, *W5 = nullptr;
    for (int i = 0; i < n_in; ++i) {
        const float* p = (const float*)d_in[i];
        switch (in_sizes[i]) {
            case 52428800: x  = p; break;  // (20, 262144, 10)
            case 640:      W1 = p; break;  // (64, 10)
            case 2048:     W2 = p; break;  // (32, 64)
            case 1024:     W3 = p; break;  // (32, 32)
            case 512:      W4 = p; break;  // (16, 32)
            case 96:       W5 = p; break;  // (6, 16)
            default: break;
        }
    }
    float* out = (float*)d_out;
    // 4 warps per block = 4 output-quarters; 32 lanes x E=2 -> 64 elements per block
    lif_kernel<<<BATCH / 64, 128>>>(x, W1, W2, W3, W4, W5, out);
}

// round 13
// speedup vs baseline: 2.0357x; 2.0357x over previous
#include <cuda_runtime.h>

#define BATCH   262144
#define T_STEPS 20
#define THRESHF 1.0f

using u32 = unsigned int;
using u64 = unsigned long long;

__device__ __forceinline__ u64 pack2(float lo, float hi) {
    u64 r; asm("mov.b64 %0, {%1, %2};" : "=l"(r) : "f"(lo), "f"(hi)); return r;
}
__device__ __forceinline__ void unpack2(u64 v, float &lo, float &hi) {
    asm("mov.b64 {%0, %1}, %2;" : "=f"(lo), "=f"(hi) : "l"(v));
}
__device__ __forceinline__ u64 packi(u32 lo, u32 hi) {
    u64 r; asm("mov.b64 %0, {%1, %2};" : "=l"(r) : "r"(lo), "r"(hi)); return r;
}
__device__ __forceinline__ void unpacki(u64 v, u32 &lo, u32 &hi) {
    asm("mov.b64 {%0, %1}, %2;" : "=r"(lo), "=r"(hi) : "l"(v));
}
// Packed dual fp32 FMA / ADD (fma pipe, 2 lanes per instruction)
__device__ __forceinline__ u64 ffma2(u64 a, u64 b, u64 c) {
    u64 d; asm("fma.rn.f32x2 %0, %1, %2, %3;" : "=l"(d) : "l"(a), "l"(b), "l"(c)); return d;
}
__device__ __forceinline__ u64 add2(u64 a, u64 b) {
    u64 d; asm("add.rn.f32x2 %0, %1, %2;" : "=l"(d) : "l"(a), "l"(b)); return d;
}

#define ONE2  0x3F8000003F800000ull   // (1.0f, 1.0f)
#define BETA2 0x3F6666663F666666ull   // (0.9f, 0.9f)

// ---- static smem weights, quarter-contiguous (warp-uniform addressing) ----
__shared__ u64 sW1[4 * 10 * 8];  // 10 -> 64, P4=8
__shared__ u64 sW2[4 * 64 * 4];  // 64 -> 32, P4=4
__shared__ u64 sW3[4 * 32 * 4];  // 32 -> 32, P4=4
__shared__ u64 sW4[4 * 32 * 2];  // 32 -> 16, P4=2
__shared__ u64 sW5[4 * 16 * 1];  // 16 -> 6 (padded to 8), P4=1
// spike-mask exchange: [region][wq][lane][el0,el1] (u32 units; u64 accesses)
__shared__ u32 spk[4 * 4 * 32 * 2];

__device__ __forceinline__ void stage(u64* dst, const float* __restrict__ W,
                                      int NIN, int NOUT, int P4, int tid) {
    int total = 4 * NIN * P4;
    for (int idx = tid; idx < total; idx += 128) {
        int q = idx / (NIN * P4);
        int r = idx % (NIN * P4);
        int i = r / P4, p = r % P4;
        int j0 = q * (2 * P4) + 2 * p;
        float a = (j0     < NOUT) ? W[j0 * NIN + i]       : 0.0f;
        float b = (j0 + 1 < NOUT) ? W[(j0 + 1) * NIN + i] : 0.0f;
        dst[idx] = pack2(a, b);
    }
}

// Packed LIF: reset from OLD m (subtract), update, return 2-bit spike mask.
// a + (-1.0f) == a - 1.0f exactly; a + 0.0f differs from a - 0.0f only in the
// sign of zero, which can never flip a (> 1.0) compare -> outputs bit-identical
// to the reference fmaf(beta, m, cur - r) chain.
__device__ __forceinline__ u32 lif_pk(u64 acc, u64 &m) {
    float mlo, mhi; unpack2(m, mlo, mhi);
    float nr0 = mlo > THRESHF ? -1.0f : 0.0f;
    float nr1 = mhi > THRESHF ? -1.0f : 0.0f;
    m = ffma2(BETA2, m, add2(acc, pack2(nr0, nr1)));
    float o0, o1; unpack2(m, o0, o1);
    u32 k = 0;
    if (o0 > THRESHF) k |= 1u;
    if (o1 > THRESHF) k |= 2u;
    return k;
}

__global__ __launch_bounds__(128, 3) void lif_kernel(
    const float* __restrict__ x,
    const float* __restrict__ W1, const float* __restrict__ W2,
    const float* __restrict__ W3, const float* __restrict__ W4,
    const float* __restrict__ W5, float* __restrict__ out)
{
    const int tid = threadIdx.x;
    stage(sW1, W1, 10, 64, 8, tid);
    stage(sW2, W2, 64, 32, 4, tid);
    stage(sW3, W3, 32, 32, 4, tid);
    stage(sW4, W4, 32, 16, 2, tid);
    stage(sW5, W5, 16,  6, 1, tid);
    __syncthreads();

    const int wq   = tid >> 5;      // warp = quarter of every layer's outputs
    const int lane = tid & 31;
    const size_t eglob = (size_t)blockIdx.x * 64 + lane * 2;  // elements 2*lane, 2*lane+1

    const u64* w1 = sW1 + wq * (10 * 8);
    const u64* w2 = sW2 + wq * (64 * 4);
    const u64* w3 = sW3 + wq * (32 * 4);
    const u64* w4 = sW4 + wq * (32 * 2);
    const u64* w5 = sW5 + wq * 16;
    u32* sp1 = spk;           // each region: [4 wq][32 lane][2 el]
    u32* sp2 = spk + 256;
    u32* sp3 = spk + 512;
    u32* sp4 = spk + 768;
    const int myoff = wq * 64 + lane * 2;   // producer u32 offset (u64-aligned)

    // membrane state as packed pairs: quarter of every layer, E=2 elements
    u64 m1[2][8], m2[2][4], m3[2][4], m4[2][2], m5[2][1];
#pragma unroll
    for (int el = 0; el < 2; ++el) {
#pragma unroll
        for (int k = 0; k < 8; ++k) m1[el][k] = 0ull;
#pragma unroll
        for (int k = 0; k < 4; ++k) { m2[el][k] = 0ull; m3[el][k] = 0ull; }
#pragma unroll
        for (int k = 0; k < 2; ++k)  m4[el][k] = 0ull;
        m5[el][0] = 0ull;
    }

#pragma unroll 1
    for (int t = 0; t < T_STEPS; ++t) {
        // ================= Layer 1: 10 -> 64 (8 pairs per warp) =================
        u32 m16[2];
#pragma unroll
        for (int el = 0; el < 2; ++el) {
            const float2* xp = (const float2*)(x + ((size_t)t * BATCH + eglob + el) * 10);
            float2 xv[5];
#pragma unroll
            for (int i = 0; i < 5; ++i) xv[i] = xp[i];

            u64 acc[8];
#pragma unroll
            for (int p = 0; p < 8; ++p) acc[p] = 0ull;
#pragma unroll
            for (int i = 0; i < 10; ++i) {
                const ulonglong2* wp = (const ulonglong2*)(w1 + i * 8);
                ulonglong2 wa = wp[0], wb = wp[1], wc = wp[2], wd = wp[3];
                float xf = (i & 1) ? xv[i >> 1].y : xv[i >> 1].x;
                u64 xd = pack2(xf, xf);
                acc[0] = ffma2(xd, wa.x, acc[0]);
                acc[1] = ffma2(xd, wa.y, acc[1]);
                acc[2] = ffma2(xd, wb.x, acc[2]);
                acc[3] = ffma2(xd, wb.y, acc[3]);
                acc[4] = ffma2(xd, wc.x, acc[4]);
                acc[5] = ffma2(xd, wc.y, acc[5]);
                acc[6] = ffma2(xd, wd.x, acc[6]);
                acc[7] = ffma2(xd, wd.y, acc[7]);
            }
            u32 mk = 0;
#pragma unroll
            for (int p = 0; p < 8; ++p)
                mk |= lif_pk(acc[p], m1[el][p]) << (2 * p);
            m16[el] = mk;
        }
        // prefetch next step's x (80 contiguous bytes for both elements) into L2
        {
            size_t tn = (t + 1 < T_STEPS) ? (size_t)(t + 1) : (size_t)t;
            const char* nx = (const char*)(x + (tn * BATCH + eglob) * 10);
            asm volatile("prefetch.global.L2 [%0];" :: "l"(nx));
            asm volatile("prefetch.global.L2 [%0];" :: "l"(nx + 79));
        }
        {   // store both elements' pre-shifted words as one STS.64
            u32 s0 = (wq & 1) ? (m16[0] << 16) : m16[0];
            u32 s1 = (wq & 1) ? (m16[1] << 16) : m16[1];
            *(u64*)(sp1 + myoff) = packi(s0, s1);
        }
        __syncthreads();
        u32 lo[2], hi[2];
        {
            u64 v0 = *(const u64*)(sp1 + 0 * 64 + lane * 2);
            u64 v1 = *(const u64*)(sp1 + 1 * 64 + lane * 2);
            u64 v2 = *(const u64*)(sp1 + 2 * 64 + lane * 2);
            u64 v3 = *(const u64*)(sp1 + 3 * 64 + lane * 2);
            u64 vlo = v0 | v1, vhi = v2 | v3;
            unpacki(vlo, lo[0], lo[1]);   // L1 outputs 0..31 per element
            unpacki(vhi, hi[0], hi[1]);   // L1 outputs 32..63 per element
        }

        // ================= Layer 2: 64 -> 32 (4 pairs per warp) =================
        u64 acc2[2][4];
#pragma unroll
        for (int el = 0; el < 2; ++el)
#pragma unroll
            for (int p = 0; p < 4; ++p) acc2[el][p] = 0ull;
#pragma unroll
        for (int i = 0; i < 64; ++i) {
            const ulonglong2* wp = (const ulonglong2*)(w2 + i * 4);
            ulonglong2 wa = wp[0], wb = wp[1];
            u32 bit = 1u << (i & 31);
            u64 h0 = (((i < 32) ? lo[0] : hi[0]) & bit) ? ONE2 : 0ull;
            u64 h1 = (((i < 32) ? lo[1] : hi[1]) & bit) ? ONE2 : 0ull;
            acc2[0][0] = ffma2(h0, wa.x, acc2[0][0]);
            acc2[0][1] = ffma2(h0, wa.y, acc2[0][1]);
            acc2[0][2] = ffma2(h0, wb.x, acc2[0][2]);
            acc2[0][3] = ffma2(h0, wb.y, acc2[0][3]);
            acc2[1][0] = ffma2(h1, wa.x, acc2[1][0]);
            acc2[1][1] = ffma2(h1, wa.y, acc2[1][1]);
            acc2[1][2] = ffma2(h1, wb.x, acc2[1][2]);
            acc2[1][3] = ffma2(h1, wb.y, acc2[1][3]);
        }
        {
            u32 w0 = 0, w1m = 0;
#pragma unroll
            for (int p = 0; p < 4; ++p) {
                w0  |= lif_pk(acc2[0][p], m2[0][p]) << (2 * p);
                w1m |= lif_pk(acc2[1][p], m2[1][p]) << (2 * p);
            }
            *(u64*)(sp2 + myoff) = packi(w0 << (wq * 8), w1m << (wq * 8));
        }
        __syncthreads();
        u32 f2[2];
        {
            u64 v = (*(const u64*)(sp2 + 0 * 64 + lane * 2))
                  | (*(const u64*)(sp2 + 1 * 64 + lane * 2))
                  | (*(const u64*)(sp2 + 2 * 64 + lane * 2))
                  | (*(const u64*)(sp2 + 3 * 64 + lane * 2));
            unpacki(v, f2[0], f2[1]);
        }

        // ================= Layer 3: 32 -> 32 =================
        u64 acc3[2][4];
#pragma unroll
        for (int el = 0; el < 2; ++el)
#pragma unroll
            for (int p = 0; p < 4; ++p) acc3[el][p] = 0ull;
#pragma unroll
        for (int i = 0; i < 32; ++i) {
            const ulonglong2* wp = (const ulonglong2*)(w3 + i * 4);
            ulonglong2 wa = wp[0], wb = wp[1];
            u32 bit = 1u << i;
            u64 h0 = (f2[0] & bit) ? ONE2 : 0ull;
            u64 h1 = (f2[1] & bit) ? ONE2 : 0ull;
            acc3[0][0] = ffma2(h0, wa.x, acc3[0][0]);
            acc3[0][1] = ffma2(h0, wa.y, acc3[0][1]);
            acc3[0][2] = ffma2(h0, wb.x, acc3[0][2]);
            acc3[0][3] = ffma2(h0, wb.y, acc3[0][3]);
            acc3[1][0] = ffma2(h1, wa.x, acc3[1][0]);
            acc3[1][1] = ffma2(h1, wa.y, acc3[1][1]);
            acc3[1][2] = ffma2(h1, wb.x, acc3[1][2]);
            acc3[1][3] = ffma2(h1, wb.y, acc3[1][3]);
        }
        {
            u32 w0 = 0, w1m = 0;
#pragma unroll
            for (int p = 0; p < 4; ++p) {
                w0  |= lif_pk(acc3[0][p], m3[0][p]) << (2 * p);
                w1m |= lif_pk(acc3[1][p], m3[1][p]) << (2 * p);
            }
            *(u64*)(sp3 + myoff) = packi(w0 << (wq * 8), w1m << (wq * 8));
        }
        __syncthreads();
        u32 f3[2];
        {
            u64 v = (*(const u64*)(sp3 + 0 * 64 + lane * 2))
                  | (*(const u64*)(sp3 + 1 * 64 + lane * 2))
                  | (*(const u64*)(sp3 + 2 * 64 + lane * 2))
                  | (*(const u64*)(sp3 + 3 * 64 + lane * 2));
            unpacki(v, f3[0], f3[1]);
        }

        // ================= Layer 4: 32 -> 16 (2 pairs per warp) =================
        u64 acc4[2][2];
#pragma unroll
        for (int el = 0; el < 2; ++el) { acc4[el][0] = 0ull; acc4[el][1] = 0ull; }
#pragma unroll
        for (int i = 0; i < 32; ++i) {
            const ulonglong2* wp = (const ulonglong2*)(w4 + i * 2);
            ulonglong2 wa = wp[0];
            u32 bit = 1u << i;
            u64 h0 = (f3[0] & bit) ? ONE2 : 0ull;
            u64 h1 = (f3[1] & bit) ? ONE2 : 0ull;
            acc4[0][0] = ffma2(h0, wa.x, acc4[0][0]);
            acc4[0][1] = ffma2(h0, wa.y, acc4[0][1]);
            acc4[1][0] = ffma2(h1, wa.x, acc4[1][0]);
            acc4[1][1] = ffma2(h1, wa.y, acc4[1][1]);
        }
        {
            u32 w0  = lif_pk(acc4[0][0], m4[0][0]) | (lif_pk(acc4[0][1], m4[0][1]) << 2);
            u32 w1m = lif_pk(acc4[1][0], m4[1][0]) | (lif_pk(acc4[1][1], m4[1][1]) << 2);
            *(u64*)(sp4 + myoff) = packi(w0 << (wq * 4), w1m << (wq * 4));
        }
        __syncthreads();
        u32 f4[2];
        {
            u64 v = (*(const u64*)(sp4 + 0 * 64 + lane * 2))
                  | (*(const u64*)(sp4 + 1 * 64 + lane * 2))
                  | (*(const u64*)(sp4 + 2 * 64 + lane * 2))
                  | (*(const u64*)(sp4 + 3 * 64 + lane * 2));
            unpacki(v, f4[0], f4[1]);
        }

        // ================= Layer 5: 16 -> 6 (padded; 1 pair per warp) ============
        u64 acc5[2];
        acc5[0] = 0ull; acc5[1] = 0ull;
#pragma unroll
        for (int i = 0; i < 16; ++i) {
            u64 w = w5[i];
            u32 bit = 1u << i;
            u64 h0 = (f4[0] & bit) ? ONE2 : 0ull;
            u64 h1 = (f4[1] & bit) ? ONE2 : 0ull;
            acc5[0] = ffma2(h0, w, acc5[0]);
            acc5[1] = ffma2(h1, w, acc5[1]);
        }
#pragma unroll
        for (int el = 0; el < 2; ++el) {
            float mlo, mhi; unpack2(m5[el][0], mlo, mhi);
            float nr0 = mlo > THRESHF ? -1.0f : 0.0f;
            float nr1 = mhi > THRESHF ? -1.0f : 0.0f;
            m5[el][0] = ffma2(BETA2, m5[el][0], add2(acc5[el], pack2(nr0, nr1)));
            float o0, o1; unpack2(m5[el][0], o0, o1);
            if (wq < 3) {
                float2 o;
                o.x = o0 > THRESHF ? 1.0f : 0.0f;
                o.y = o1 > THRESHF ? 1.0f : 0.0f;
                *(float2*)(out + ((size_t)t * BATCH + eglob + el) * 6 + wq * 2) = o;
            }
        }
    }
}

extern "C" void kernel_launch(void* const* d_in, const int* in_sizes, int n_in,
                              void* d_out, int out_size) {
    const float *x = nullptr, *W1 = nullptr, *W2 = nullptr, *W3 = nullptr,
                *W4 = nullptr, *W5 = nullptr;
    for (int i = 0; i < n_in; ++i) {
        const float* p = (const float*)d_in[i];
        switch (in_sizes[i]) {
            case 52428800: x  = p; break;  // (20, 262144, 10)
            case 640:      W1 = p; break;  // (64, 10)
            case 2048:     W2 = p; break;  // (32, 64)
            case 1024:     W3 = p; break;  // (32, 32)
            case 512:      W4 = p; break;  // (16, 32)
            case 96:       W5 = p; break;  // (6, 16)
            default: break;
        }
    }
    float* out = (float*)d_out;
    // 4 warps per block = 4 output-quarters; 32 lanes x E=2 -> 64 elements per block
    lif_kernel<<<BATCH / 64, 128>>>(x, W1, W2, W3, W4, W5, out);
}